// round 13
// baseline (speedup 1.0000x reference)
#include <cuda_runtime.h>
#include <cuda_fp16.h>
#include <math.h>
#include <stdint.h>

// Problem dims
#define NB 8
#define LQ 1024
#define SK 4096
#define DM 512
#define ML (NB*LQ)   // 8192
#define MS (NB*SK)   // 32768
#define BKH 64       // k-chunk (halves) per stage = four k16 MMA steps
#define PADK 72      // padded row stride in halves (conflict-free LDS + LDSM)
#define NSTAGE 3
#define SMEM_BYTES (NSTAGE * 2 * 128 * PADK * 2)   // 110592

// ---------------------------------------------------------------------------
// Scratch (device globals: no allocations allowed)
// ---------------------------------------------------------------------------
__device__ __half g_xh [ML*DM];
__device__ __half g_sh [MS*DM];
__device__ __half g_q  [ML*DM];
__device__ __half g_k  [MS*DM];
__device__ __half g_vT [(size_t)NB*DM*SK];
__device__ float  g_q2 [ML];
__device__ float  g_k2 [MS];
__device__ float  g_scf[(size_t)NB*LQ*SK];   // fp32 distances
__device__ __half g_sc [(size_t)NB*LQ*SK];   // fp16 attn weights
__device__ __half g_ms [ML*DM];
__device__ float  g_mm [ML*DM];
__device__ __half g_m1 [ML*DM];
__device__ __half g_u  [ML*2*DM];
__device__ float  g_z  [ML*DM];
__device__ __half g_WqT[DM*DM];
__device__ __half g_WkT[DM*DM];
__device__ __half g_WvT[DM*DM];
__device__ __half g_WmT[DM*DM];
__device__ __half g_W1T[2*DM*2*DM];
__device__ __half g_W2T[DM*2*DM];

__device__ __forceinline__ uint32_t s2u(const void* p) {
    uint32_t a;
    asm("{ .reg .u64 t; cvta.to.shared.u64 t, %1; cvt.u32.u64 %0, t; }" : "=r"(a) : "l"(p));
    return a;
}

__device__ __forceinline__ void mma_f16(float c[4], const unsigned a[4], const unsigned b[2]) {
    asm("mma.sync.aligned.m16n8k16.row.col.f32.f16.f16.f32 "
        "{%0,%1,%2,%3}, {%4,%5,%6,%7}, {%8,%9}, {%0,%1,%2,%3};"
        : "+f"(c[0]), "+f"(c[1]), "+f"(c[2]), "+f"(c[3])
        : "r"(a[0]), "r"(a[1]), "r"(a[2]), "r"(a[3]), "r"(b[0]), "r"(b[1]));
}

__device__ __forceinline__ void ldsm4(unsigned r[4], uint32_t addr) {
    asm volatile("ldmatrix.sync.aligned.m8n8.x4.shared.b16 {%0,%1,%2,%3}, [%4];"
        : "=r"(r[0]), "=r"(r[1]), "=r"(r[2]), "=r"(r[3]) : "r"(addr));
}

__device__ __forceinline__ void cp16(uint32_t dst, const void* src) {
    asm volatile("cp.async.cg.shared.global [%0], [%1], 16;" :: "r"(dst), "l"(src));
}

// ---------------------------------------------------------------------------
// fp16 tensor-core GEMM (fp32 accumulate): C[M,N] = A[M,K] @ B'[N,K]^T  (NT)
// fp16 operands in gmem, 3-stage cp.async pipeline (BK=64/stage, one barrier
// per stage), ldmatrix fragment loads SOFTWARE-PIPELINED (ping-pong: load
// fragments for k16 step i+1 while HMMAs for step i run), 256 threads = 8
// warps (4m x 2n), warp tile 32x64 via m16n8k16, 2 CTAs/SM.
// MODE 0: plain   MODE 1: dist = sqrt(max(e0[m]+e1[n]-2*acc, 0))
// MODE 2: A = virtual concat [A | A1] along K (each half lda), relu epilogue
// OT = float or __half output.
// smem layout (dynamic): As[stage][128][PADK] then Bs[stage][128][PADK]
// ---------------------------------------------------------------------------
template<int MODE, typename OT>
__global__ __launch_bounds__(256, 2)
void hgemm_k(const __half* __restrict__ A, const __half* __restrict__ A1,
             const __half* __restrict__ B, OT* __restrict__ C,
             int K, int lda, int ldb, int ldc,
             long sA, long sB, long sC,
             const float* __restrict__ e0, const float* __restrict__ e1,
             int se0, int se1)
{
    extern __shared__ __align__(16) __half smem[];
    __half* AsBase = smem;                         // NSTAGE * 128*PADK
    __half* BsBase = smem + NSTAGE * 128 * PADK;   // NSTAGE * 128*PADK

    const int z = blockIdx.z;
    A += (long)z * sA;
    if (MODE == 2) A1 += (long)z * sA;
    B += (long)z * sB;
    C += (long)z * sC;
    const float* E0 = (MODE == 1) ? (e0 + (long)z * se0) : nullptr;
    const float* E1 = (MODE == 1) ? (e1 + (long)z * se1) : nullptr;

    const int t  = threadIdx.x;
    const int m0 = blockIdx.y * 128;
    const int n0 = blockIdx.x * 128;

    const int warpId = t >> 5;
    const int lane   = t & 31;
    const int mb     = (warpId >> 1) * 32;   // 0,32,64,96
    const int nb     = (warpId & 1) * 64;    // 0,64
    const int gq     = lane >> 2;            // 0..7
    const int tg     = lane & 3;             // 0..3

    // ldmatrix per-lane source rows/cols
    const int lrowA = lane & 15;
    const int kcolA = (lane >> 4) * 8;
    const int lrowB = ((lane >> 4) << 3) + (lane & 7);
    const int kcolB = ((lane >> 3) & 1) * 8;

    // staging: tile = 128 rows x 64 halves = 1024 16B-chunks/operand, 4/thread
    const int rs = t >> 3;
    const int c8 = (t & 7) * 8;

    float acc[2][8][4];
#pragma unroll
    for (int i = 0; i < 2; i++)
#pragma unroll
        for (int j = 0; j < 8; j++)
#pragma unroll
            for (int r = 0; r < 4; r++) acc[i][j][r] = 0.f;

    const int NKT = K / BKH;

    auto stage = [&](int kt, int b) {
        __half* As = AsBase + b * 128 * PADK;
        __half* Bs = BsBase + b * 128 * PADK;
        const int k0 = kt * BKH;
        const __half* Asrc = A; int kk0 = k0;
        if (MODE == 2 && k0 >= DM) { Asrc = A1; kk0 = k0 - DM; }
#pragma unroll
        for (int i = 0; i < 4; i++) {
            const int row = rs + i * 32;
            cp16(s2u(As + row * PADK + c8), Asrc + (long)(m0 + row) * lda + kk0 + c8);
        }
#pragma unroll
        for (int i = 0; i < 4; i++) {
            const int row = rs + i * 32;
            cp16(s2u(Bs + row * PADK + c8), B + (long)(n0 + row) * ldb + k0 + c8);
        }
        asm volatile("cp.async.commit_group;");
    };

    stage(0, 0);
    stage(1, 1);

    // ping-pong fragment buffers
    unsigned afr[2][2][4], bfr[2][8][2];

    for (int kt = 0; kt < NKT; kt++) {
        const int buf = kt % NSTAGE;
        asm volatile("cp.async.wait_group 1;");
        __syncthreads();
        if (kt + 2 < NKT) stage(kt + 2, (kt + 2) % NSTAGE);

        const uint32_t baseA = s2u(AsBase + buf * 128 * PADK);
        const uint32_t baseB = s2u(BsBase + buf * 128 * PADK);

        auto load_frags = [&](int ks, int pb) {
#pragma unroll
            for (int i = 0; i < 2; i++)
                ldsm4(afr[pb][i], baseA + (uint32_t)((mb + i * 16 + lrowA) * PADK + ks + kcolA) * 2u);
#pragma unroll
            for (int j2 = 0; j2 < 4; j2++) {
                unsigned r[4];
                ldsm4(r, baseB + (uint32_t)((nb + j2 * 16 + lrowB) * PADK + ks + kcolB) * 2u);
                bfr[pb][2*j2    ][0] = r[0]; bfr[pb][2*j2    ][1] = r[1];
                bfr[pb][2*j2 + 1][0] = r[2]; bfr[pb][2*j2 + 1][1] = r[3];
            }
        };

        load_frags(0, 0);
#pragma unroll
        for (int s4 = 0; s4 < 4; s4++) {
            const int pb = s4 & 1;
            if (s4 < 3) load_frags((s4 + 1) * 16, pb ^ 1);
#pragma unroll
            for (int i = 0; i < 2; i++)
#pragma unroll
                for (int j = 0; j < 8; j++)
                    mma_f16(acc[i][j], afr[pb][i], bfr[pb][j]);
        }
    }

    // ---- epilogue (fragment: c0,c1 = row gq, cols 2tg..+1; c2,c3 = row gq+8)
#pragma unroll
    for (int i = 0; i < 2; i++) {
        const int row0 = m0 + mb + i * 16 + gq;
        const int row1 = row0 + 8;
#pragma unroll
        for (int j = 0; j < 8; j++) {
            const int col0 = n0 + nb + j * 8 + tg * 2;
            float v00 = acc[i][j][0], v01 = acc[i][j][1];
            float v10 = acc[i][j][2], v11 = acc[i][j][3];
            if (MODE == 1) {
                const float e00 = E0[row0], e01 = E0[row1];
                const float f0 = E1[col0], f1 = E1[col0 + 1];
                v00 = sqrtf(fmaxf(e00 + f0 - 2.f * v00, 0.f));
                v01 = sqrtf(fmaxf(e00 + f1 - 2.f * v01, 0.f));
                v10 = sqrtf(fmaxf(e01 + f0 - 2.f * v10, 0.f));
                v11 = sqrtf(fmaxf(e01 + f1 - 2.f * v11, 0.f));
            }
            if (MODE == 2) {
                v00 = fmaxf(v00, 0.f); v01 = fmaxf(v01, 0.f);
                v10 = fmaxf(v10, 0.f); v11 = fmaxf(v11, 0.f);
            }
            if constexpr (sizeof(OT) == 2) {
                *reinterpret_cast<__half2*>((__half*)C + (long)row0 * ldc + col0) = __floats2half2_rn(v00, v01);
                *reinterpret_cast<__half2*>((__half*)C + (long)row1 * ldc + col0) = __floats2half2_rn(v10, v11);
            } else {
                *reinterpret_cast<float2*>((float*)C + (long)row0 * ldc + col0) = make_float2(v00, v01);
                *reinterpret_cast<float2*>((float*)C + (long)row1 * ldc + col0) = make_float2(v10, v11);
            }
        }
    }
}

// ---------------------------------------------------------------------------
// Fused prep: fp32->fp16 conversion of x and source, plus all 6 weight
// transposes (fp32 [R,C] -> fp16 [C,R]), dispatched by blockIdx.x range.
// ---------------------------------------------------------------------------
#define XBLK (ML*DM/1024)          // 4096
#define SBLK (MS*DM/1024)          // 16384
#define TQ   256                   // 512x512 -> (512/32)*(512/32)
#define TW1  1024                  // 1024x1024
#define TW2  512                   // W2 [1024,512]: (512/32)*(1024/32)

__global__ __launch_bounds__(256)
void prep_k(const float* __restrict__ x, const float* __restrict__ src,
            __half* __restrict__ xh, __half* __restrict__ sh,
            const float* __restrict__ Wq, const float* __restrict__ Wk,
            const float* __restrict__ Wv, const float* __restrict__ Wm,
            const float* __restrict__ W1, const float* __restrict__ W2,
            __half* __restrict__ wqT, __half* __restrict__ wkT,
            __half* __restrict__ wvT, __half* __restrict__ wmT,
            __half* __restrict__ w1T, __half* __restrict__ w2T)
{
    int b = blockIdx.x;
    if (b < XBLK + SBLK) {
        const float* in = (b < XBLK) ? x : src;
        __half* outp    = (b < XBLK) ? xh : sh;
        const long base = (b < XBLK) ? (long)b * 1024 : (long)(b - XBLK) * 1024;
        const long i = base + threadIdx.x * 4;
        float4 v = *reinterpret_cast<const float4*>(in + i);
        *reinterpret_cast<__half2*>(outp + i)     = __floats2half2_rn(v.x, v.y);
        *reinterpret_cast<__half2*>(outp + i + 2) = __floats2half2_rn(v.z, v.w);
        return;
    }
    b -= XBLK + SBLK;
    const float* in; __half* outp; int R, C, tile;
    if      (b < TQ)                    { in = Wq; outp = wqT; R = DM;   C = DM;   tile = b; }
    else if (b < 2*TQ)                  { in = Wk; outp = wkT; R = DM;   C = DM;   tile = b - TQ; }
    else if (b < 3*TQ)                  { in = Wv; outp = wvT; R = DM;   C = DM;   tile = b - 2*TQ; }
    else if (b < 4*TQ)                  { in = Wm; outp = wmT; R = DM;   C = DM;   tile = b - 3*TQ; }
    else if (b < 4*TQ + TW1)            { in = W1; outp = w1T; R = 2*DM; C = 2*DM; tile = b - 4*TQ; }
    else                                { in = W2; outp = w2T; R = 2*DM; C = DM;   tile = b - 4*TQ - TW1; }
    const int ntx = C / 32;
    const int c0 = (tile % ntx) * 32, r0 = (tile / ntx) * 32;
    __shared__ float tf[32][33];
    const int tx = threadIdx.x & 31, ty = threadIdx.x >> 5;
#pragma unroll
    for (int i = 0; i < 32; i += 8)
        tf[ty + i][tx] = in[(long)(r0 + ty + i) * C + c0 + tx];
    __syncthreads();
#pragma unroll
    for (int i = 0; i < 32; i += 8)
        outp[(long)(c0 + ty + i) * R + r0 + tx] = __float2half_rn(tf[tx][ty + i]);
}

// Row squared-norms over fp16 rows of 512 for q then k, fp32 accumulate.
__global__ __launch_bounds__(256)
void rownorm2_k(const __half* __restrict__ Q, const __half* __restrict__ Kk,
                float* __restrict__ oq, float* __restrict__ ok)
{
    int row  = blockIdx.x * 8 + (threadIdx.x >> 5);
    const int lane = threadIdx.x & 31;
    const __half* X; float* o;
    if (row < ML) { X = Q; o = oq; }
    else          { X = Kk; o = ok; row -= ML; }
    const __half2* p = reinterpret_cast<const __half2*>(X + (long)row * DM);
    float s = 0.f;
#pragma unroll
    for (int c = 0; c < 8; c++) {
        float2 v = __half22float2(p[lane + c * 32]);
        s = fmaf(v.x, v.x, fmaf(v.y, v.y, s));
    }
#pragma unroll
    for (int o2 = 16; o2; o2 >>= 1) s += __shfl_xor_sync(0xffffffffu, s, o2);
    if (lane == 0) o[row] = s;
}

// Softmax over rows of 4096: read fp32 dist, write fp16 attn. One block/row.
__global__ __launch_bounds__(256)
void softmax_fh(const float* __restrict__ scf, __half* __restrict__ sc)
{
    const float* p = scf + (long)blockIdx.x * 4096;
    __half* o = sc + (long)blockIdx.x * 4096;
    const int t = threadIdx.x;
    float4 vals[4];
    float mx = -1e30f;
#pragma unroll
    for (int i = 0; i < 4; i++) {
        vals[i] = *reinterpret_cast<const float4*>(p + t * 16 + i * 4);
        mx = fmaxf(mx, fmaxf(fmaxf(vals[i].x, vals[i].y), fmaxf(vals[i].z, vals[i].w)));
    }
    __shared__ float red[256];
    red[t] = mx; __syncthreads();
    for (int oo = 128; oo; oo >>= 1) { if (t < oo) red[t] = fmaxf(red[t], red[t + oo]); __syncthreads(); }
    mx = red[0]; __syncthreads();
    float s = 0.f;
#pragma unroll
    for (int i = 0; i < 4; i++) {
        vals[i].x = __expf(vals[i].x - mx); vals[i].y = __expf(vals[i].y - mx);
        vals[i].z = __expf(vals[i].z - mx); vals[i].w = __expf(vals[i].w - mx);
        s += vals[i].x + vals[i].y + vals[i].z + vals[i].w;
    }
    red[t] = s; __syncthreads();
    for (int oo = 128; oo; oo >>= 1) { if (t < oo) red[t] += red[t + oo]; __syncthreads(); }
    const float inv = 1.f / red[0];
#pragma unroll
    for (int i = 0; i < 4; i++) {
        __half2 h0 = __floats2half2_rn(vals[i].x * inv, vals[i].y * inv);
        __half2 h1 = __floats2half2_rn(vals[i].z * inv, vals[i].w * inv);
        *reinterpret_cast<__half2*>(o + t * 16 + i * 4)     = h0;
        *reinterpret_cast<__half2*>(o + t * 16 + i * 4 + 2) = h1;
    }
}

// LayerNorm over fp32 rows of 512; optional fp32 residual; OT output.
template<typename OT>
__global__ __launch_bounds__(256)
void ln_k(const float* __restrict__ X, const float* __restrict__ g,
          const float* __restrict__ b, const float* __restrict__ res,
          OT* __restrict__ out)
{
    const long row = blockIdx.x;
    const float* p = X + row * 512;
    const int t = threadIdx.x;
    float v0 = p[t], v1 = p[t + 256];
    __shared__ float red[256];
    red[t] = v0 + v1; __syncthreads();
    for (int o = 128; o; o >>= 1) { if (t < o) red[t] += red[t + o]; __syncthreads(); }
    const float mu = red[0] * (1.f / 512.f);
    __syncthreads();
    const float d0 = v0 - mu, d1 = v1 - mu;
    red[t] = d0 * d0 + d1 * d1; __syncthreads();
    for (int o = 128; o; o >>= 1) { if (t < o) red[t] += red[t + o]; __syncthreads(); }
    const float rs = rsqrtf(red[0] * (1.f / 512.f) + 1e-5f);
    float o0 = d0 * rs * g[t]       + b[t];
    float o1 = d1 * rs * g[t + 256] + b[t + 256];
    if (res) { o0 += res[row * 512 + t]; o1 += res[row * 512 + t + 256]; }
    if constexpr (sizeof(OT) == 2) {
        out[row * 512 + t]       = __float2half_rn(o0);
        out[row * 512 + t + 256] = __float2half_rn(o1);
    } else {
        out[row * 512 + t]       = o0;
        out[row * 512 + t + 256] = o1;
    }
}

template <typename P, typename T>
static P sym(T& s) { void* p = nullptr; cudaGetSymbolAddress(&p, s); return (P)p; }

extern "C" void kernel_launch(void* const* d_in, const int* in_sizes, int n_in,
                              void* d_out, int out_size)
{
    const float* x   = (const float*)d_in[0];
    const float* src = (const float*)d_in[1];
    const float* Wq  = (const float*)d_in[2];
    const float* Wk  = (const float*)d_in[3];
    const float* Wv  = (const float*)d_in[4];
    const float* Wm  = (const float*)d_in[5];
    const float* W1  = (const float*)d_in[6];
    const float* W2  = (const float*)d_in[7];
    const float* g1  = (const float*)d_in[8];
    const float* b1  = (const float*)d_in[9];
    const float* g2  = (const float*)d_in[10];
    const float* b2  = (const float*)d_in[11];
    float* out = (float*)d_out;

    __half *xh = sym<__half*>(g_xh), *sh = sym<__half*>(g_sh);
    __half *q  = sym<__half*>(g_q),  *k  = sym<__half*>(g_k),  *vT = sym<__half*>(g_vT);
    __half *sc = sym<__half*>(g_sc), *ms = sym<__half*>(g_ms), *m1 = sym<__half*>(g_m1);
    __half *u  = sym<__half*>(g_u);
    float  *scf = sym<float*>(g_scf);
    float  *q2 = sym<float*>(g_q2),  *k2 = sym<float*>(g_k2);
    float  *mm = sym<float*>(g_mm),  *zz = sym<float*>(g_z);
    __half *wqT = sym<__half*>(g_WqT), *wkT = sym<__half*>(g_WkT), *wvT = sym<__half*>(g_WvT);
    __half *wmT = sym<__half*>(g_WmT), *w1T = sym<__half*>(g_W1T), *w2T = sym<__half*>(g_W2T);

    // opt-in to 108KB dynamic smem (idempotent)
    cudaFuncSetAttribute(hgemm_k<0, __half>, cudaFuncAttributeMaxDynamicSharedMemorySize, SMEM_BYTES);
    cudaFuncSetAttribute(hgemm_k<0, float>,  cudaFuncAttributeMaxDynamicSharedMemorySize, SMEM_BYTES);
    cudaFuncSetAttribute(hgemm_k<1, float>,  cudaFuncAttributeMaxDynamicSharedMemorySize, SMEM_BYTES);
    cudaFuncSetAttribute(hgemm_k<2, __half>, cudaFuncAttributeMaxDynamicSharedMemorySize, SMEM_BYTES);

    // 0: fused prep (x/src -> fp16, all weight transposes -> fp16 K-major)
    prep_k<<<XBLK + SBLK + 4*TQ + TW1 + TW2, 256>>>(x, src, xh, sh,
        Wq, Wk, Wv, Wm, W1, W2, wqT, wkT, wvT, wmT, w1T, w2T);

    // 1-2: q/k projections (flattened over batch)
    hgemm_k<0, __half><<<dim3(DM/128, ML/128, 1), 256, SMEM_BYTES>>>(xh, nullptr, wqT, q, DM, DM, DM, DM, 0, 0, 0, nullptr, nullptr, 0, 0);
    hgemm_k<0, __half><<<dim3(DM/128, MS/128, 1), 256, SMEM_BYTES>>>(sh, nullptr, wkT, k, DM, DM, DM, DM, 0, 0, 0, nullptr, nullptr, 0, 0);

    // 3: vT = (src @ Wv)^T computed directly: C[d][s] = sum_k WvT[d][k]*src[s][k]
    hgemm_k<0, __half><<<dim3(SK/128, DM/128, NB), 256, SMEM_BYTES>>>(wvT, nullptr, sh, vT,
        DM, DM, DM, SK, 0, (long)SK*DM, (long)DM*SK, nullptr, nullptr, 0, 0);

    // 4: squared row norms for q and k (one launch)
    rownorm2_k<<<(ML + MS) / 8, 256>>>(q, k, q2, k2);

    // 5: dist = sqrt(max(q2 + k2 - 2 q.k, 0))  (batched NT, fused epilogue, fp32 out)
    hgemm_k<1, float><<<dim3(SK/128, LQ/128, NB), 256, SMEM_BYTES>>>(q, nullptr, k, scf,
        DM, DM, DM, SK, (long)LQ*DM, (long)SK*DM, (long)LQ*SK, q2, k2, LQ, SK);

    // 6: softmax over S (fp32 in, fp16 out)
    softmax_fh<<<ML, 256>>>(scf, sc);

    // 7: message = attn @ v  (A = attn [LQ,SK], B' = vT [DM,SK])
    hgemm_k<0, __half><<<dim3(DM/128, LQ/128, NB), 256, SMEM_BYTES>>>(sc, nullptr, vT, ms,
        SK, SK, SK, DM, (long)LQ*SK, (long)DM*SK, (long)LQ*DM, nullptr, nullptr, 0, 0);

    // 8: mm = message @ Wm  (fp32 out -> layernorm)
    hgemm_k<0, float><<<dim3(DM/128, ML/128, 1), 256, SMEM_BYTES>>>(ms, nullptr, wmT, mm, DM, DM, DM, DM, 0, 0, 0, nullptr, nullptr, 0, 0);

    // 9: layernorm1 -> fp16
    ln_k<__half><<<ML, 256>>>(mm, g1, b1, nullptr, m1);

    // 10: u = relu([x | m1] @ W1)  (fused concat + relu, fp16 out)
    hgemm_k<2, __half><<<dim3(2*DM/128, ML/128, 1), 256, SMEM_BYTES>>>(xh, m1, w1T, u, 2*DM, DM, 2*DM, 2*DM, 0, 0, 0, nullptr, nullptr, 0, 0);

    // 11: z = u @ W2  (fp32 out -> layernorm)
    hgemm_k<0, float><<<dim3(DM/128, ML/128, 1), 256, SMEM_BYTES>>>(u, nullptr, w2T, zz, 2*DM, 2*DM, 2*DM, DM, 0, 0, 0, nullptr, nullptr, 0, 0);

    // 12: out = x + layernorm2(z)
    ln_k<float><<<ML, 256>>>(zz, g2, b2, x, out);
}